// round 1
// baseline (speedup 1.0000x reference)
#include <cuda_runtime.h>
#include <cstddef>

// ---------------------------------------------------------------------------
// DeepFM fused pipeline.
// Shapes: N=8192 samples, F=45 fields (permuted), E=256 embed dim.
// K1: gather W2 rows, FM first+second order, x1 = deep @ l1_w^T   (the 6 GFLOP op)
// K2: column mean/scale of x1 (BN1 stats)
// K3: h1 = BN1(x1); x2 = h1 @ l2_w^T + l2_b
// K4: column mean/scale of x2 (BN2 stats)
// K5: out[n] = fm[n] + sum_j BN2(x2)[n,j] + bias
// ---------------------------------------------------------------------------

#define NS 8192
#define NF 45
#define NE 256
#define KTOT (NF*NE)   // 11520

__constant__ int cPERM[45] = {
    0,1,2,3,4,5,6, 7,8,9,
    10,11,12,13,14,15,16,17,18,19,20,21,22,23,
    26,27, 28,29, 24,25,
    30,31,32,33,34,35,36,37,38,39,40,41,42,43,44
};
__constant__ int cFOFF[45] = {
    0,300,1300,2300,2800,2950,2962,
    2993,2993,2993,
    3023,3023,3023,3023,3023,3023,3023,3023,3023,3023,3023,3023,3023,3023,
    3223,3223, 53223,53223, 103223,103223,
    123223,123223,123223,123223,123223,123223,123223,123223,
    123223,123223,123223,123223,123223,123223,123223
};

// Scratch (device globals: no cudaMalloc allowed)
__device__ float g_x1[NS*32];
__device__ float g_x2[NS*32];
__device__ float g_fm[NS];
__device__ float g_mean1[32], g_scale1[32];
__device__ float g_mean2[32], g_scale2[32];

// ---- packed f32x2 helpers (sm_100+) ----
__device__ __forceinline__ unsigned long long pack2(float lo, float hi) {
    unsigned long long r;
    asm("mov.b64 %0, {%1, %2};" : "=l"(r) : "f"(lo), "f"(hi));
    return r;
}
__device__ __forceinline__ void unpack2(unsigned long long v, float &lo, float &hi) {
    asm("mov.b64 {%0, %1}, %2;" : "=f"(lo), "=f"(hi) : "l"(v));
}
__device__ __forceinline__ void fma2(unsigned long long &d,
                                     unsigned long long a,
                                     unsigned long long b) {
    asm("fma.rn.f32x2 %0, %1, %2, %0;" : "+l"(d) : "l"(a), "l"(b));
}

// ---------------------------------------------------------------------------
// K1: 64 samples per block, 128 threads.
// Gather role: thread t -> sample gn = t>>1, half part = t&1 (32 k-values each).
// GEMM role:   thread t -> rows 4*(t&15)..+3, cols 4*(t>>4)..+3 (4x4 microtile,
//              accumulated as f32x2 row-pairs).
// ---------------------------------------------------------------------------
__global__ __launch_bounds__(128) void k1_kernel(
    const int*   __restrict__ Xi,
    const float* __restrict__ Xv,
    const float* __restrict__ W1,
    const float* __restrict__ W2,
    const float* __restrict__ L1W)
{
    __shared__ __align__(16) float sEs[64*64];           // e tile, [kk][n]
    __shared__ unsigned long long sLs[64*32];            // l1_w tile, [kk][j], value duplicated in both halves
    __shared__ float sFm1[64];
    __shared__ float sFm2[128];

    const int t  = threadIdx.x;
    const int n0 = blockIdx.x * 64;

    const int gn   = t >> 1;
    const int part = t & 1;
    const int tn   = t & 15;
    const int tj   = t >> 4;

    unsigned long long acc[2][4];
#pragma unroll
    for (int p = 0; p < 2; ++p)
#pragma unroll
        for (int j = 0; j < 4; ++j) acc[p][j] = 0ULL;

    float fm1 = 0.f;
    sFm2[part*64 + gn] = 0.f;

    const int sample = n0 + gn;
    const int lj   = t >> 2;     // 0..31  (l1_w row owner)
    const int lseg = t & 3;      // 0..3

    for (int kc = 0; kc < 4; ++kc) {
        float sreg[32], qreg[32];
#pragma unroll
        for (int i = 0; i < 32; ++i) { sreg[i] = 0.f; qreg[i] = 0.f; }

        for (int c = 0; c < 45; ++c) {
            // ---- gather one field's embedding chunk (64 of 256 dims) ----
            const int   col = cPERM[c];
            const int   xi  = Xi[sample*45 + col];
            const float xv  = Xv[sample*45 + col];
            const float4* wsrc = reinterpret_cast<const float4*>(
                W2 + (size_t)(xi + cFOFF[c]) * 256 + kc*64 + part*32);
            float4 v[8];
#pragma unroll
            for (int i = 0; i < 8; ++i) v[i] = wsrc[i];

            if (kc == 0 && part == 0) fm1 += W1[xi + cFOFF[c]] * xv;

#pragma unroll
            for (int i = 0; i < 8; ++i) {
                const int kk = part*32 + i*4;
                float e0 = v[i].x * xv, e1 = v[i].y * xv;
                float e2 = v[i].z * xv, e3 = v[i].w * xv;
                sEs[(kk+0)*64 + gn] = e0;
                sEs[(kk+1)*64 + gn] = e1;
                sEs[(kk+2)*64 + gn] = e2;
                sEs[(kk+3)*64 + gn] = e3;
                sreg[i*4+0] += e0; qreg[i*4+0] += e0*e0;
                sreg[i*4+1] += e1; qreg[i*4+1] += e1*e1;
                sreg[i*4+2] += e2; qreg[i*4+2] += e2*e2;
                sreg[i*4+3] += e3; qreg[i*4+3] += e3*e3;
            }

            // ---- stage l1_w chunk: 32 rows x 64 k, duplicated into f32x2 ----
            {
                const float4* l4 = reinterpret_cast<const float4*>(
                    L1W + (size_t)lj * KTOT + c*256 + kc*64 + lseg*16);
#pragma unroll
                for (int i = 0; i < 4; ++i) {
                    float4 lv = l4[i];
                    const int kk = lseg*16 + i*4;
                    sLs[(kk+0)*32 + lj] = pack2(lv.x, lv.x);
                    sLs[(kk+1)*32 + lj] = pack2(lv.y, lv.y);
                    sLs[(kk+2)*32 + lj] = pack2(lv.z, lv.z);
                    sLs[(kk+3)*32 + lj] = pack2(lv.w, lv.w);
                }
            }
            __syncthreads();

            // ---- 64x32 GEMM accumulate over 64 k with packed f32x2 ----
#pragma unroll
            for (int kk = 0; kk < 64; ++kk) {
                const ulonglong2 ev = *reinterpret_cast<const ulonglong2*>(
                    &sEs[kk*64 + tn*4]);
                const unsigned long long* lrow = &sLs[kk*32 + tj*4];
                unsigned long long l0 = lrow[0], l1 = lrow[1];
                unsigned long long l2 = lrow[2], l3 = lrow[3];
                fma2(acc[0][0], ev.x, l0);
                fma2(acc[0][1], ev.x, l1);
                fma2(acc[0][2], ev.x, l2);
                fma2(acc[0][3], ev.x, l3);
                fma2(acc[1][0], ev.y, l0);
                fma2(acc[1][1], ev.y, l1);
                fma2(acc[1][2], ev.y, l2);
                fma2(acc[1][3], ev.y, l3);
            }
            __syncthreads();
        }

        // FM second order partial for this k-chunk: sum_k (s^2 - q)
        float loc = 0.f;
#pragma unroll
        for (int i = 0; i < 32; ++i) loc += sreg[i]*sreg[i] - qreg[i];
        sFm2[part*64 + gn] += loc;
    }

    if (part == 0) sFm1[gn] = fm1;
    __syncthreads();

    // write x1 tile
#pragma unroll
    for (int p = 0; p < 2; ++p)
#pragma unroll
        for (int jj = 0; jj < 4; ++jj) {
            float a, b;
            unpack2(acc[p][jj], a, b);
            const int row = n0 + tn*4 + p*2;
            g_x1[(size_t)row     * 32 + tj*4 + jj] = a;
            g_x1[(size_t)(row+1) * 32 + tj*4 + jj] = b;
        }

    if (t < 64)
        g_fm[n0 + t] = sFm1[t] + 0.5f * (sFm2[t] + sFm2[64 + t]);
}

// ---------------------------------------------------------------------------
// K2/K4: per-column mean and BN scale (g * rsqrt(var+eps)), population var.
// One block per column, 256 threads.
// ---------------------------------------------------------------------------
__global__ void stats_kernel(const float* __restrict__ src,
                             const float* __restrict__ gamma,
                             float* __restrict__ mean_out,
                             float* __restrict__ scale_out)
{
    const int j = blockIdx.x;
    const int t = threadIdx.x;
    float s = 0.f, ss = 0.f;
    for (int n = t; n < NS; n += 256) {
        float v = src[(size_t)n*32 + j];
        s  += v;
        ss += v*v;
    }
    __shared__ float rs[256], rss[256];
    rs[t] = s; rss[t] = ss;
    __syncthreads();
    for (int off = 128; off > 0; off >>= 1) {
        if (t < off) { rs[t] += rs[t+off]; rss[t] += rss[t+off]; }
        __syncthreads();
    }
    if (t == 0) {
        float m   = rs[0]  * (1.f/NS);
        float var = rss[0] * (1.f/NS) - m*m;
        mean_out[j]  = m;
        scale_out[j] = gamma[j] * rsqrtf(var + 1e-5f);
    }
}

// ---------------------------------------------------------------------------
// K3: h1 = BN1(x1); x2 = h1 @ l2_w^T + l2_b.  One thread per sample.
// ---------------------------------------------------------------------------
__global__ __launch_bounds__(128) void layer2_kernel(
    const float* __restrict__ l2w,
    const float* __restrict__ l2b,
    const float* __restrict__ bn1_b)
{
    __shared__ float sw[32*32];
    __shared__ float sb[32];
    __shared__ float sm[32], ssc[32], sbb[32];
    const int t = threadIdx.x;
#pragma unroll
    for (int i = t; i < 1024; i += 128) sw[i] = l2w[i];
    if (t < 32) {
        sb[t]  = l2b[t];
        sm[t]  = g_mean1[t];
        ssc[t] = g_scale1[t];
        sbb[t] = bn1_b[t];
    }
    __syncthreads();

    const int n = blockIdx.x * 128 + t;
    float h[32];
#pragma unroll
    for (int i = 0; i < 32; ++i) {
        float x = g_x1[(size_t)n*32 + i];
        h[i] = (x - sm[i]) * ssc[i] + sbb[i];
    }
    for (int jj = 0; jj < 32; ++jj) {
        float a = sb[jj];
        const float* wrow = &sw[jj*32];
#pragma unroll
        for (int i = 0; i < 32; ++i) a += h[i] * wrow[i];
        g_x2[(size_t)n*32 + jj] = a;
    }
}

// ---------------------------------------------------------------------------
// K5: final combine.
// ---------------------------------------------------------------------------
__global__ __launch_bounds__(128) void final_kernel(
    const float* __restrict__ bias,
    const float* __restrict__ bn2_b,
    float* __restrict__ out)
{
    __shared__ float sm[32], ssc[32], sbb[32];
    const int t = threadIdx.x;
    if (t < 32) { sm[t] = g_mean2[t]; ssc[t] = g_scale2[t]; sbb[t] = bn2_b[t]; }
    __syncthreads();

    const int n = blockIdx.x * 128 + t;
    float a = g_fm[n] + bias[0];
#pragma unroll
    for (int j = 0; j < 32; ++j)
        a += (g_x2[(size_t)n*32 + j] - sm[j]) * ssc[j] + sbb[j];
    out[n] = a;
}

// ---------------------------------------------------------------------------
extern "C" void kernel_launch(void* const* d_in, const int* in_sizes, int n_in,
                              void* d_out, int out_size)
{
    const int*   Xi    = (const int*)  d_in[0];
    const float* Xv    = (const float*)d_in[1];
    const float* W1    = (const float*)d_in[2];
    const float* W2    = (const float*)d_in[3];
    const float* bias  = (const float*)d_in[4];
    const float* l1_w  = (const float*)d_in[5];
    // d_in[6] = l1_b : cancels exactly inside BN1 (constant shift per column)
    const float* bn1_g = (const float*)d_in[7];
    const float* bn1_b = (const float*)d_in[8];
    const float* l2_w  = (const float*)d_in[9];
    const float* l2_b  = (const float*)d_in[10];
    const float* bn2_g = (const float*)d_in[11];
    const float* bn2_b = (const float*)d_in[12];
    float* out = (float*)d_out;

    float *x1p, *x2p, *m1, *s1, *m2, *s2;
    cudaGetSymbolAddress((void**)&x1p, g_x1);
    cudaGetSymbolAddress((void**)&x2p, g_x2);
    cudaGetSymbolAddress((void**)&m1,  g_mean1);
    cudaGetSymbolAddress((void**)&s1,  g_scale1);
    cudaGetSymbolAddress((void**)&m2,  g_mean2);
    cudaGetSymbolAddress((void**)&s2,  g_scale2);

    k1_kernel<<<NS/64, 128>>>(Xi, Xv, W1, W2, l1_w);
    stats_kernel<<<32, 256>>>(x1p, bn1_g, m1, s1);
    layer2_kernel<<<NS/128, 128>>>(l2_w, l2_b, bn1_b);
    stats_kernel<<<32, 256>>>(x2p, bn2_g, m2, s2);
    final_kernel<<<NS/128, 128>>>(bias, bn2_b, out);
}

// round 2
// speedup vs baseline: 1.0488x; 1.0488x over previous
#include <cuda_runtime.h>
#include <cstddef>

// ---------------------------------------------------------------------------
// DeepFM fused pipeline.
// Shapes: N=8192 samples, F=45 fields (permuted), E=256 embed dim.
// K1: gather W2 rows, FM first+second order, x1 = deep @ l1_w^T   (the 6 GFLOP op)
// K2: column mean/scale of x1 (BN1 stats)
// K3: h1 = BN1(x1); x2 = h1 @ l2_w^T + l2_b
// K4: column mean/scale of x2 (BN2 stats)
// K5: out[n] = fm[n] + sum_j BN2(x2)[n,j] + bias
// ---------------------------------------------------------------------------

#define NS 8192
#define NF 45
#define NE 256
#define KTOT (NF*NE)   // 11520

__constant__ int cPERM[45] = {
    0,1,2,3,4,5,6, 7,8,9,
    10,11,12,13,14,15,16,17,18,19,20,21,22,23,
    26,27, 28,29, 24,25,
    30,31,32,33,34,35,36,37,38,39,40,41,42,43,44
};
__constant__ int cFOFF[45] = {
    0,300,1300,2300,2800,2950,2962,
    2993,2993,2993,
    3023,3023,3023,3023,3023,3023,3023,3023,3023,3023,3023,3023,3023,3023,
    3223,3223, 53223,53223, 103223,103223,
    123223,123223,123223,123223,123223,123223,123223,123223,
    123223,123223,123223,123223,123223,123223,123223
};

// Scratch (device globals: no cudaMalloc allowed)
__device__ float g_x1[NS*32];
__device__ float g_x2[NS*32];
__device__ float g_fm[NS];
__device__ float g_mean1[32], g_scale1[32];
__device__ float g_mean2[32], g_scale2[32];

// ---- packed f32x2 helpers (sm_100+) ----
__device__ __forceinline__ unsigned long long pack2(float lo, float hi) {
    unsigned long long r;
    asm("mov.b64 %0, {%1, %2};" : "=l"(r) : "f"(lo), "f"(hi));
    return r;
}
__device__ __forceinline__ void unpack2(unsigned long long v, float &lo, float &hi) {
    asm("mov.b64 {%0, %1}, %2;" : "=f"(lo), "=f"(hi) : "l"(v));
}
__device__ __forceinline__ void fma2(unsigned long long &d,
                                     unsigned long long a,
                                     unsigned long long b) {
    asm("fma.rn.f32x2 %0, %1, %2, %0;" : "+l"(d) : "l"(a), "l"(b));
}

// ---------------------------------------------------------------------------
// K1: 64 samples per block, 128 threads.
// Gather role: thread t -> sample gn = t>>1, half part = t&1 (32 k-values each).
// GEMM role:   thread t -> rows 4*(t&15)..+3, cols 4*(t>>4)..+3 (4x4 microtile,
//              accumulated as f32x2 row-pairs).
// ---------------------------------------------------------------------------
__global__ __launch_bounds__(128) void k1_kernel(
    const int*   __restrict__ Xi,
    const float* __restrict__ Xv,
    const float* __restrict__ W1,
    const float* __restrict__ W2,
    const float* __restrict__ L1W)
{
    __shared__ __align__(16) float sEs[64*64];           // e tile, [kk][n]
    __shared__ unsigned long long sLs[64*32];            // l1_w tile, [kk][j], value duplicated in both halves
    __shared__ float sFm1[64];
    __shared__ float sFm2[128];

    const int t  = threadIdx.x;
    const int n0 = blockIdx.x * 64;

    const int gn   = t >> 1;
    const int part = t & 1;
    const int tn   = t & 15;
    const int tj   = t >> 4;

    unsigned long long acc[2][4];
#pragma unroll
    for (int p = 0; p < 2; ++p)
#pragma unroll
        for (int j = 0; j < 4; ++j) acc[p][j] = 0ULL;

    float fm1 = 0.f;
    sFm2[part*64 + gn] = 0.f;

    const int sample = n0 + gn;
    const int lj   = t >> 2;     // 0..31  (l1_w row owner)
    const int lseg = t & 3;      // 0..3

    for (int kc = 0; kc < 4; ++kc) {
        float sreg[32], qreg[32];
#pragma unroll
        for (int i = 0; i < 32; ++i) { sreg[i] = 0.f; qreg[i] = 0.f; }

        for (int c = 0; c < 45; ++c) {
            // ---- gather one field's embedding chunk (64 of 256 dims) ----
            const int   col = cPERM[c];
            const int   xi  = Xi[sample*45 + col];
            const float xv  = Xv[sample*45 + col];
            const float4* wsrc = reinterpret_cast<const float4*>(
                W2 + (size_t)(xi + cFOFF[c]) * 256 + kc*64 + part*32);
            float4 v[8];
#pragma unroll
            for (int i = 0; i < 8; ++i) v[i] = wsrc[i];

            if (kc == 0 && part == 0) fm1 += W1[xi + cFOFF[c]] * xv;

#pragma unroll
            for (int i = 0; i < 8; ++i) {
                const int kk = part*32 + i*4;
                float e0 = v[i].x * xv, e1 = v[i].y * xv;
                float e2 = v[i].z * xv, e3 = v[i].w * xv;
                sEs[(kk+0)*64 + gn] = e0;
                sEs[(kk+1)*64 + gn] = e1;
                sEs[(kk+2)*64 + gn] = e2;
                sEs[(kk+3)*64 + gn] = e3;
                sreg[i*4+0] += e0; qreg[i*4+0] += e0*e0;
                sreg[i*4+1] += e1; qreg[i*4+1] += e1*e1;
                sreg[i*4+2] += e2; qreg[i*4+2] += e2*e2;
                sreg[i*4+3] += e3; qreg[i*4+3] += e3*e3;
            }

            // ---- stage l1_w chunk: 32 rows x 64 k, duplicated into f32x2 ----
            {
                const float4* l4 = reinterpret_cast<const float4*>(
                    L1W + (size_t)lj * KTOT + c*256 + kc*64 + lseg*16);
#pragma unroll
                for (int i = 0; i < 4; ++i) {
                    float4 lv = l4[i];
                    const int kk = lseg*16 + i*4;
                    sLs[(kk+0)*32 + lj] = pack2(lv.x, lv.x);
                    sLs[(kk+1)*32 + lj] = pack2(lv.y, lv.y);
                    sLs[(kk+2)*32 + lj] = pack2(lv.z, lv.z);
                    sLs[(kk+3)*32 + lj] = pack2(lv.w, lv.w);
                }
            }
            __syncthreads();

            // ---- 64x32 GEMM accumulate over 64 k with packed f32x2 ----
#pragma unroll
            for (int kk = 0; kk < 64; ++kk) {
                const ulonglong2 ev = *reinterpret_cast<const ulonglong2*>(
                    &sEs[kk*64 + tn*4]);
                const unsigned long long* lrow = &sLs[kk*32 + tj*4];
                unsigned long long l0 = lrow[0], l1 = lrow[1];
                unsigned long long l2 = lrow[2], l3 = lrow[3];
                fma2(acc[0][0], ev.x, l0);
                fma2(acc[0][1], ev.x, l1);
                fma2(acc[0][2], ev.x, l2);
                fma2(acc[0][3], ev.x, l3);
                fma2(acc[1][0], ev.y, l0);
                fma2(acc[1][1], ev.y, l1);
                fma2(acc[1][2], ev.y, l2);
                fma2(acc[1][3], ev.y, l3);
            }
            __syncthreads();
        }

        // FM second order partial for this k-chunk: sum_k (s^2 - q)
        float loc = 0.f;
#pragma unroll
        for (int i = 0; i < 32; ++i) loc += sreg[i]*sreg[i] - qreg[i];
        sFm2[part*64 + gn] += loc;
    }

    if (part == 0) sFm1[gn] = fm1;
    __syncthreads();

    // write x1 tile
#pragma unroll
    for (int p = 0; p < 2; ++p)
#pragma unroll
        for (int jj = 0; jj < 4; ++jj) {
            float a, b;
            unpack2(acc[p][jj], a, b);
            const int row = n0 + tn*4 + p*2;
            g_x1[(size_t)row     * 32 + tj*4 + jj] = a;
            g_x1[(size_t)(row+1) * 32 + tj*4 + jj] = b;
        }

    if (t < 64)
        g_fm[n0 + t] = sFm1[t] + 0.5f * (sFm2[t] + sFm2[64 + t]);
}

// ---------------------------------------------------------------------------
// K2/K4: per-column mean and BN scale (g * rsqrt(var+eps)), population var.
// One block per column, 256 threads.
// ---------------------------------------------------------------------------
__global__ void stats_kernel(const float* __restrict__ src,
                             const float* __restrict__ gamma,
                             float* __restrict__ mean_out,
                             float* __restrict__ scale_out)
{
    const int j = blockIdx.x;
    const int t = threadIdx.x;
    float s = 0.f, ss = 0.f;
    for (int n = t; n < NS; n += 256) {
        float v = src[(size_t)n*32 + j];
        s  += v;
        ss += v*v;
    }
    __shared__ float rs[256], rss[256];
    rs[t] = s; rss[t] = ss;
    __syncthreads();
    for (int off = 128; off > 0; off >>= 1) {
        if (t < off) { rs[t] += rs[t+off]; rss[t] += rss[t+off]; }
        __syncthreads();
    }
    if (t == 0) {
        float m   = rs[0]  * (1.f/NS);
        float var = rss[0] * (1.f/NS) - m*m;
        mean_out[j]  = m;
        scale_out[j] = gamma[j] * rsqrtf(var + 1e-5f);
    }
}

// ---------------------------------------------------------------------------
// K3: h1 = BN1(x1); x2 = h1 @ l2_w^T + l2_b.  One thread per sample.
// ---------------------------------------------------------------------------
__global__ __launch_bounds__(128) void layer2_kernel(
    const float* __restrict__ l2w,
    const float* __restrict__ l2b,
    const float* __restrict__ bn1_b)
{
    __shared__ float sw[32*32];
    __shared__ float sb[32];
    __shared__ float sm[32], ssc[32], sbb[32];
    const int t = threadIdx.x;
#pragma unroll
    for (int i = t; i < 1024; i += 128) sw[i] = l2w[i];
    if (t < 32) {
        sb[t]  = l2b[t];
        sm[t]  = g_mean1[t];
        ssc[t] = g_scale1[t];
        sbb[t] = bn1_b[t];
    }
    __syncthreads();

    const int n = blockIdx.x * 128 + t;
    float h[32];
#pragma unroll
    for (int i = 0; i < 32; ++i) {
        float x = g_x1[(size_t)n*32 + i];
        h[i] = (x - sm[i]) * ssc[i] + sbb[i];
    }
    for (int jj = 0; jj < 32; ++jj) {
        float a = sb[jj];
        const float* wrow = &sw[jj*32];
#pragma unroll
        for (int i = 0; i < 32; ++i) a += h[i] * wrow[i];
        g_x2[(size_t)n*32 + jj] = a;
    }
}

// ---------------------------------------------------------------------------
// K5: final combine.
// ---------------------------------------------------------------------------
__global__ __launch_bounds__(128) void final_kernel(
    const float* __restrict__ bias,
    const float* __restrict__ bn2_b,
    float* __restrict__ out)
{
    __shared__ float sm[32], ssc[32], sbb[32];
    const int t = threadIdx.x;
    if (t < 32) { sm[t] = g_mean2[t]; ssc[t] = g_scale2[t]; sbb[t] = bn2_b[t]; }
    __syncthreads();

    const int n = blockIdx.x * 128 + t;
    float a = g_fm[n] + bias[0];
#pragma unroll
    for (int j = 0; j < 32; ++j)
        a += (g_x2[(size_t)n*32 + j] - sm[j]) * ssc[j] + sbb[j];
    out[n] = a;
}

// ---------------------------------------------------------------------------
extern "C" void kernel_launch(void* const* d_in, const int* in_sizes, int n_in,
                              void* d_out, int out_size)
{
    const int*   Xi    = (const int*)  d_in[0];
    const float* Xv    = (const float*)d_in[1];
    const float* W1    = (const float*)d_in[2];
    const float* W2    = (const float*)d_in[3];
    const float* bias  = (const float*)d_in[4];
    const float* l1_w  = (const float*)d_in[5];
    // d_in[6] = l1_b : cancels exactly inside BN1 (constant shift per column)
    const float* bn1_g = (const float*)d_in[7];
    const float* bn1_b = (const float*)d_in[8];
    const float* l2_w  = (const float*)d_in[9];
    const float* l2_b  = (const float*)d_in[10];
    const float* bn2_g = (const float*)d_in[11];
    const float* bn2_b = (const float*)d_in[12];
    float* out = (float*)d_out;

    float *x1p, *x2p, *m1, *s1, *m2, *s2;
    cudaGetSymbolAddress((void**)&x1p, g_x1);
    cudaGetSymbolAddress((void**)&x2p, g_x2);
    cudaGetSymbolAddress((void**)&m1,  g_mean1);
    cudaGetSymbolAddress((void**)&s1,  g_scale1);
    cudaGetSymbolAddress((void**)&m2,  g_mean2);
    cudaGetSymbolAddress((void**)&s2,  g_scale2);

    k1_kernel<<<NS/64, 128>>>(Xi, Xv, W1, W2, l1_w);
    stats_kernel<<<32, 256>>>(x1p, bn1_g, m1, s1);
    layer2_kernel<<<NS/128, 128>>>(l2_w, l2_b, bn1_b);
    stats_kernel<<<32, 256>>>(x2p, bn2_g, m2, s2);
    final_kernel<<<NS/128, 128>>>(bias, bn2_b, out);
}

// round 4
// speedup vs baseline: 3.2404x; 3.0895x over previous
#include <cuda_runtime.h>
#include <cuda_bf16.h>
#include <cstdint>
#include <cstddef>

#define NS   8192
#define KTOT 11520

__constant__ int cPERM[45] = {
    0,1,2,3,4,5,6, 7,8,9,
    10,11,12,13,14,15,16,17,18,19,20,21,22,23,
    26,27, 28,29, 24,25,
    30,31,32,33,34,35,36,37,38,39,40,41,42,43,44
};
__constant__ int cFOFF[45] = {
    0,300,1300,2300,2800,2950,2962,
    2993,2993,2993,
    3023,3023,3023,3023,3023,3023,3023,3023,3023,3023,3023,3023,3023,3023,
    3223,3223, 53223,53223, 103223,103223,
    123223,123223,123223,123223,123223,123223,123223,123223,
    123223,123223,123223,123223,123223,123223,123223
};

// device-global scratch (no cudaMalloc allowed)
__device__ float g_x1p[2*NS*32];
__device__ float g_x2[NS*32];
__device__ float g_fmp[2*NS];
__device__ float g_acc[128];                 // [sum1|ss1|sum2|ss2] x32
__device__ __align__(16) unsigned char g_Bh[180*4096];   // l1_w hi tiles 32x64 bf16
__device__ __align__(16) unsigned char g_Bl[180*4096];   // l1_w lo tiles

// ---------------- helpers ----------------
__device__ __forceinline__ uint32_t smem_u32(const void* p) {
    uint32_t r;
    asm("{ .reg .u64 t; cvta.to.shared.u64 t, %1; cvt.u32.u64 %0, t; }"
        : "=r"(r) : "l"(p));
    return r;
}
// pack two f32 -> bf16x2 (second arg -> low half)
__device__ __forceinline__ uint32_t cvt2(float hi, float lo) {
    uint32_t r;
    asm("cvt.rn.bf16x2.f32 %0, %1, %2;" : "=r"(r) : "f"(hi), "f"(lo));
    return r;
}
__device__ __forceinline__ void ldsm4(uint32_t* r, uint32_t addr) {
    asm volatile("ldmatrix.sync.aligned.m8n8.x4.shared.b16 {%0,%1,%2,%3}, [%4];"
        : "=r"(r[0]), "=r"(r[1]), "=r"(r[2]), "=r"(r[3]) : "r"(addr));
}
__device__ __forceinline__ void mma16816(float* d, const uint32_t* a, const uint32_t* b) {
    asm volatile(
        "mma.sync.aligned.m16n8k16.row.col.f32.bf16.bf16.f32 "
        "{%0,%1,%2,%3}, {%4,%5,%6,%7}, {%8,%9}, {%0,%1,%2,%3};"
        : "+f"(d[0]), "+f"(d[1]), "+f"(d[2]), "+f"(d[3])
        : "r"(a[0]), "r"(a[1]), "r"(a[2]), "r"(a[3]), "r"(b[0]), "r"(b[1]));
}

// ---------------- smem layout (byte offsets into dynamic smem) ----------------
// A tiles: 128 rows x 144B (64 bf16 + pad), hi/lo, double buffered
#define A_IMG   18432u
#define SM_A(buf,img)  ((uint32_t)(((buf)*2u + (img)) * A_IMG))          // 0..73728
#define B_IMG   4608u
#define SM_B(buf,img)  ((uint32_t)(73728u + ((buf)*2u + (img)) * B_IMG)) // ..92160
#define SM_IDX  92160u
#define SM_XVo  115200u
#define K1_DYN  138240u

// ---------------------------------------------------------------------------
// prep: l1_w -> bf16 hi/lo 32x64 tile images (plain row-major, 128B rows).
// tile sid = q*45+f : rows j=0..31, cols k=0..63 -> l1w[j][f*256+q*64+k]
// ---------------------------------------------------------------------------
__global__ __launch_bounds__(128) void prep_kernel(const float* __restrict__ l1w) {
    const int sid = blockIdx.x;          // 0..179
    const int q = sid / 45, f = sid % 45;
    const int t = threadIdx.x;
    if (sid == 0 && t < 128) g_acc[t] = 0.f;
    const int j  = t >> 2;
    const int c0 = (t & 3) * 16;
    const float* src = l1w + (size_t)j * KTOT + f * 256 + q * 64 + c0;
    unsigned char* bh = g_Bh + (size_t)sid * 4096;
    unsigned char* bl = g_Bl + (size_t)sid * 4096;
#pragma unroll
    for (int i = 0; i < 16; i += 2) {
        float a = src[i], b = src[i+1];
        uint32_t h2 = cvt2(b, a);
        float fa = __uint_as_float(h2 << 16);
        float fb = __uint_as_float(h2 & 0xffff0000u);
        uint32_t l2 = cvt2(b - fb, a - fa);
        uint32_t off = (uint32_t)(j * 128 + (c0 + i) * 2);
        *(uint32_t*)(bh + off) = h2;
        *(uint32_t*)(bl + off) = l2;
    }
}

// ---------------------------------------------------------------------------
// k1: 128 blocks (64 sample-tiles x 2 K-splits) x 256 threads (8 warps).
// Per block: x1[128,32] += sum over 90 stages (field f, quarter qg) of
// A(128x64) @ B(32x64)^T via mma.sync bf16 3-term split, fp32 reg accum.
// Also FM first/second order partials.
// ---------------------------------------------------------------------------
__global__ void __launch_bounds__(256, 1) k1_kernel(
    const int*   __restrict__ Xi,
    const float* __restrict__ Xv,
    const float* __restrict__ W1,
    const float* __restrict__ W2)
{
    extern __shared__ unsigned char dyn[];
    const uint32_t sbase = smem_u32(dyn);

    const int t   = threadIdx.x;
    const int wid = t >> 5, lane = t & 31;
    const int tile = blockIdx.x >> 1, ks = blockIdx.x & 1;
    const int n0 = tile * 128;

    int*   sIdx = (int*)(dyn + SM_IDX);
    float* sXv  = (float*)(dyn + SM_XVo);
    for (int i = t; i < 128 * 45; i += 256) {
        const int smp = i / 45, f = i - smp * 45;
        sIdx[i] = Xi[(size_t)(n0 + smp) * 45 + cPERM[f]] + cFOFF[f];
        sXv[i]  = Xv[(size_t)(n0 + smp) * 45 + cPERM[f]];
    }
    __syncthreads();

    // gather role: this thread owns sample smp, half (32 dims of the quarter)
    const int smp  = wid * 16 + (lane >> 1);
    const int half = lane & 1;
    const uint32_t aw = (uint32_t)(smp * 144 + half * 64);

    // mma role: ldmatrix source coords
    const uint32_t a_row = (uint32_t)(wid * 16 + ((lane >> 3) & 1) * 8 + (lane & 7));
    const uint32_t a_col = (uint32_t)((lane >> 4) * 16);
    const uint32_t b_row = (uint32_t)((lane & 7) + ((lane >> 4) << 3));
    const uint32_t b_col = (uint32_t)(((lane >> 3) & 1) * 16);

    float acc[4][4];
#pragma unroll
    for (int i = 0; i < 4; ++i)
#pragma unroll
        for (int j = 0; j < 4; ++j) acc[i][j] = 0.f;

    float fm1 = 0.f, fmacc = 0.f;
    int stage = 0;

    for (int qq = 0; qq < 2; ++qq) {
        const int qg = ks * 2 + qq;
        float s[32], qa[32];
#pragma unroll
        for (int i = 0; i < 32; ++i) { s[i] = 0.f; qa[i] = 0.f; }

        for (int f = 0; f < 45; ++f, ++stage) {
            const int b = stage & 1;

            // ---- stage B tiles (hi/lo) into smem: 32 rows x 128B -> 144B stride
            {
                const int sid = qg * 45 + f;
                const int row = t >> 3, chunk = t & 7;
                const uint32_t goff = (uint32_t)(row * 128 + chunk * 16);
                const uint32_t soff = (uint32_t)(row * 144 + chunk * 16);
                *(uint4*)(dyn + SM_B(b,0) + soff) =
                    *(const uint4*)(g_Bh + (size_t)sid * 4096 + goff);
                *(uint4*)(dyn + SM_B(b,1) + soff) =
                    *(const uint4*)(g_Bl + (size_t)sid * 4096 + goff);
            }

            // ---- gather + convert A (this thread: 32 dims of its sample)
            const int   idx = sIdx[smp * 45 + f];
            const float xv  = sXv [smp * 45 + f];
            if (ks == 0 && qq == 0 && half == 0) fm1 += W1[idx] * xv;

            const float4* src = (const float4*)(W2 + (size_t)idx * 256) + qg * 16 + half * 8;
            unsigned char* Ah = dyn + SM_A(b,0);
            unsigned char* Al = dyn + SM_A(b,1);
#pragma unroll
            for (int i = 0; i < 8; ++i) {
                float4 v = src[i];
                float e0 = v.x * xv, e1 = v.y * xv, e2 = v.z * xv, e3 = v.w * xv;
                uint32_t h01 = cvt2(e1, e0), h23 = cvt2(e3, e2);
                float f0 = __uint_as_float(h01 << 16);
                float f1 = __uint_as_float(h01 & 0xffff0000u);
                float f2 = __uint_as_float(h23 << 16);
                float f3 = __uint_as_float(h23 & 0xffff0000u);
                uint32_t l01 = cvt2(e1 - f1, e0 - f0), l23 = cvt2(e3 - f3, e2 - f2);
                *(uint2*)(Ah + aw + i * 8) = make_uint2(h01, h23);
                *(uint2*)(Al + aw + i * 8) = make_uint2(l01, l23);
                const int ii = i * 4;
                s[ii+0] += e0; qa[ii+0] = fmaf(e0, e0, qa[ii+0]);
                s[ii+1] += e1; qa[ii+1] = fmaf(e1, e1, qa[ii+1]);
                s[ii+2] += e2; qa[ii+2] = fmaf(e2, e2, qa[ii+2]);
                s[ii+3] += e3; qa[ii+3] = fmaf(e3, e3, qa[ii+3]);
            }
            __syncthreads();

            // ---- mma phase: K=64 in 4 k16 steps, 3 split terms
            const uint32_t aAh = sbase + SM_A(b,0) + a_row * 144 + a_col;
            const uint32_t aAl = sbase + SM_A(b,1) + a_row * 144 + a_col;
            const uint32_t aB0h = sbase + SM_B(b,0) + b_row * 144 + b_col;
            const uint32_t aB1h = aB0h + 16 * 144;
            const uint32_t aB0l = sbase + SM_B(b,1) + b_row * 144 + b_col;
            const uint32_t aB1l = aB0l + 16 * 144;
#pragma unroll
            for (int k = 0; k < 4; ++k) {
                uint32_t Afh[4], Afl[4], B0h[4], B1h[4], B0l[4], B1l[4];
                ldsm4(Afh, aAh + k * 32);
                ldsm4(Afl, aAl + k * 32);
                ldsm4(B0h, aB0h + k * 32);
                ldsm4(B1h, aB1h + k * 32);
                ldsm4(B0l, aB0l + k * 32);
                ldsm4(B1l, aB1l + k * 32);
                mma16816(acc[0], Afh, &B0h[0]);
                mma16816(acc[1], Afh, &B0h[2]);
                mma16816(acc[2], Afh, &B1h[0]);
                mma16816(acc[3], Afh, &B1h[2]);
                mma16816(acc[0], Afh, &B0l[0]);
                mma16816(acc[1], Afh, &B0l[2]);
                mma16816(acc[2], Afh, &B1l[0]);
                mma16816(acc[3], Afh, &B1l[2]);
                mma16816(acc[0], Afl, &B0h[0]);
                mma16816(acc[1], Afl, &B0h[2]);
                mma16816(acc[2], Afl, &B1h[0]);
                mma16816(acc[3], Afl, &B1h[2]);
            }
            // no trailing sync: next stage writes the other buffer; the
            // following __syncthreads (after its gather) orders reuse.
        }
        float loc = 0.f;
#pragma unroll
        for (int i = 0; i < 32; ++i) loc += s[i]*s[i] - qa[i];
        fmacc += loc;
    }

    // FM partial: combine the two half-lanes of each sample
    float val = 0.5f * fmacc + fm1;
    val += __shfl_down_sync(0xffffffffu, val, 1);
    if (half == 0) g_fmp[ks * NS + n0 + smp] = val;

    // epilogue: write x1 partial from register accumulators
    {
        const int r0 = n0 + wid * 16 + (lane >> 2);
        const int cb = (lane & 3) * 2;
        float* dst = g_x1p + (size_t)ks * NS * 32;
#pragma unroll
        for (int nt = 0; nt < 4; ++nt) {
            const int c = nt * 8 + cb;
            *(float2*)(dst + (size_t)r0       * 32 + c) = make_float2(acc[nt][0], acc[nt][1]);
            *(float2*)(dst + (size_t)(r0 + 8) * 32 + c) = make_float2(acc[nt][2], acc[nt][3]);
        }
    }
}

// ---------------------------------------------------------------------------
// stats: column sum / sumsq of (a [+ b]) accumulated via atomics into g_acc.
// ---------------------------------------------------------------------------
__global__ __launch_bounds__(256) void stats_kernel(const float* __restrict__ a,
                                                    const float* __restrict__ b,
                                                    float* __restrict__ sum,
                                                    float* __restrict__ ss)
{
    const int t = threadIdx.x, col = t & 31, w = t >> 5;
    const int rbase = blockIdx.x * 64;
    float s = 0.f, sq = 0.f;
#pragma unroll
    for (int i = 0; i < 8; ++i) {
        const size_t r = rbase + w + i * 8;
        float v = a[r * 32 + col];
        if (b) v += b[r * 32 + col];
        s += v; sq += v * v;
    }
    __shared__ float sS[32], sQ[32];
    if (t < 32) { sS[t] = 0.f; sQ[t] = 0.f; }
    __syncthreads();
    atomicAdd(&sS[col], s); atomicAdd(&sQ[col], sq);
    __syncthreads();
    if (t < 32) { atomicAdd(&sum[t], sS[t]); atomicAdd(&ss[t], sQ[t]); }
}

// ---------------------------------------------------------------------------
// layer2: h = BN1(x1a+x1b); x2 = h @ l2_w^T + l2_b
// ---------------------------------------------------------------------------
__global__ __launch_bounds__(128) void layer2_kernel(const float* __restrict__ l2w,
                                                     const float* __restrict__ l2b,
                                                     const float* __restrict__ bn1g,
                                                     const float* __restrict__ bn1b)
{
    __shared__ float sw[1024], sm[32], ssc[32], sbb[32], sb[32];
    const int t = threadIdx.x;
    for (int i = t; i < 1024; i += 128) sw[i] = l2w[i];
    if (t < 32) {
        float m   = g_acc[t] * (1.f / NS);
        float var = g_acc[32 + t] * (1.f / NS) - m * m;
        sm[t] = m; ssc[t] = bn1g[t] * rsqrtf(var + 1e-5f);
        sbb[t] = bn1b[t]; sb[t] = l2b[t];
    }
    __syncthreads();
    const int n = blockIdx.x * 128 + t;
    const float* xa = g_x1p + (size_t)n * 32;
    const float* xb = g_x1p + (size_t)(NS + n) * 32;
    float h[32];
#pragma unroll
    for (int i = 0; i < 32; ++i) h[i] = (xa[i] + xb[i] - sm[i]) * ssc[i] + sbb[i];
#pragma unroll 4
    for (int j = 0; j < 32; ++j) {
        float a = sb[j];
#pragma unroll
        for (int i = 0; i < 32; ++i) a = fmaf(h[i], sw[j * 32 + i], a);
        g_x2[(size_t)n * 32 + j] = a;
    }
}

// ---------------------------------------------------------------------------
// final: out = fm partials + sum_j BN2(x2) + bias
// ---------------------------------------------------------------------------
__global__ __launch_bounds__(128) void final_kernel(const float* __restrict__ bias,
                                                    const float* __restrict__ bn2g,
                                                    const float* __restrict__ bn2b,
                                                    float* __restrict__ out)
{
    __shared__ float sm[32], ssc[32], sbb[32];
    const int t = threadIdx.x;
    if (t < 32) {
        float m   = g_acc[64 + t] * (1.f / NS);
        float var = g_acc[96 + t] * (1.f / NS) - m * m;
        sm[t] = m; ssc[t] = bn2g[t] * rsqrtf(var + 1e-5f); sbb[t] = bn2b[t];
    }
    __syncthreads();
    const int n = blockIdx.x * 128 + t;
    float a = g_fmp[n] + g_fmp[NS + n] + bias[0];
    const float* x = g_x2 + (size_t)n * 32;
#pragma unroll
    for (int j = 0; j < 32; ++j) a += (x[j] - sm[j]) * ssc[j] + sbb[j];
    out[n] = a;
}

// ---------------------------------------------------------------------------
extern "C" void kernel_launch(void* const* d_in, const int* in_sizes, int n_in,
                              void* d_out, int out_size)
{
    const int*   Xi    = (const int*)  d_in[0];
    const float* Xv    = (const float*)d_in[1];
    const float* W1    = (const float*)d_in[2];
    const float* W2    = (const float*)d_in[3];
    const float* bias  = (const float*)d_in[4];
    const float* l1_w  = (const float*)d_in[5];
    // d_in[6] = l1_b: cancels exactly inside BN1
    const float* bn1_g = (const float*)d_in[7];
    const float* bn1_b = (const float*)d_in[8];
    const float* l2_w  = (const float*)d_in[9];
    const float* l2_b  = (const float*)d_in[10];
    const float* bn2_g = (const float*)d_in[11];
    const float* bn2_b = (const float*)d_in[12];
    float* out = (float*)d_out;

    cudaFuncSetAttribute(k1_kernel, cudaFuncAttributeMaxDynamicSharedMemorySize, K1_DYN);

    float *x1p, *x2p, *accp;
    cudaGetSymbolAddress((void**)&x1p,  g_x1p);
    cudaGetSymbolAddress((void**)&x2p,  g_x2);
    cudaGetSymbolAddress((void**)&accp, g_acc);

    prep_kernel<<<180, 128>>>(l1_w);
    k1_kernel<<<128, 256, K1_DYN>>>(Xi, Xv, W1, W2);
    stats_kernel<<<128, 256>>>(x1p, x1p + (size_t)NS * 32, accp, accp + 32);
    layer2_kernel<<<64, 128>>>(l2_w, l2_b, bn1_g, bn1_b);
    stats_kernel<<<128, 256>>>(x2p, (const float*)nullptr, accp + 64, accp + 96);
    final_kernel<<<64, 128>>>(bias, bn2_g, bn2_b, out);
}

// round 5
// speedup vs baseline: 4.6375x; 1.4312x over previous
#include <cuda_runtime.h>
#include <cuda_bf16.h>
#include <cstdint>
#include <cstddef>

#define NS   8192
#define KTOT 11520

__constant__ int cPERM[45] = {
    0,1,2,3,4,5,6, 7,8,9,
    10,11,12,13,14,15,16,17,18,19,20,21,22,23,
    26,27, 28,29, 24,25,
    30,31,32,33,34,35,36,37,38,39,40,41,42,43,44
};
__constant__ int cFOFF[45] = {
    0,300,1300,2300,2800,2950,2962,
    2993,2993,2993,
    3023,3023,3023,3023,3023,3023,3023,3023,3023,3023,3023,3023,3023,3023,
    3223,3223, 53223,53223, 103223,103223,
    123223,123223,123223,123223,123223,123223,123223,123223,
    123223,123223,123223,123223,123223,123223,123223
};

// device-global scratch (no cudaMalloc allowed)
__device__ float g_x1p[2*NS*32];
__device__ float g_x2[NS*32];
__device__ float g_fmp[2*NS];
__device__ float g_acc[128];                 // [sum1|ss1|sum2|ss2] x32
__device__ __align__(16) unsigned char g_Bh[180*4096];   // l1_w hi tiles 32x64 bf16
__device__ __align__(16) unsigned char g_Bl[180*4096];   // l1_w lo tiles

// ---------------- helpers ----------------
__device__ __forceinline__ uint32_t smem_u32(const void* p) {
    uint32_t r;
    asm("{ .reg .u64 t; cvta.to.shared.u64 t, %1; cvt.u32.u64 %0, t; }"
        : "=r"(r) : "l"(p));
    return r;
}
// pack two f32 -> bf16x2 (second arg -> low half)
__device__ __forceinline__ uint32_t cvt2(float hi, float lo) {
    uint32_t r;
    asm("cvt.rn.bf16x2.f32 %0, %1, %2;" : "=r"(r) : "f"(hi), "f"(lo));
    return r;
}
__device__ __forceinline__ void ldsm4(uint32_t* r, uint32_t addr) {
    asm volatile("ldmatrix.sync.aligned.m8n8.x4.shared.b16 {%0,%1,%2,%3}, [%4];"
        : "=r"(r[0]), "=r"(r[1]), "=r"(r[2]), "=r"(r[3]) : "r"(addr));
}
__device__ __forceinline__ void mma16816(float* d, const uint32_t* a, const uint32_t* b) {
    asm volatile(
        "mma.sync.aligned.m16n8k16.row.col.f32.bf16.bf16.f32 "
        "{%0,%1,%2,%3}, {%4,%5,%6,%7}, {%8,%9}, {%0,%1,%2,%3};"
        : "+f"(d[0]), "+f"(d[1]), "+f"(d[2]), "+f"(d[3])
        : "r"(a[0]), "r"(a[1]), "r"(a[2]), "r"(a[3]), "r"(b[0]), "r"(b[1]));
}
__device__ __forceinline__ void cpa16(uint32_t dst, const void* src) {
    asm volatile("cp.async.cg.shared.global [%0], [%1], 16;" :: "r"(dst), "l"(src));
}
__device__ __forceinline__ void cpa_commit() {
    asm volatile("cp.async.commit_group;" ::: "memory");
}
__device__ __forceinline__ void cpa_wait0() {
    asm volatile("cp.async.wait_group 0;" ::: "memory");
}

// ---------------- smem layout (byte offsets into dynamic smem) ----------------
// A tiles: 128 rows x 144B (64 bf16 + pad), hi/lo, double buffered
#define A_IMG   18432u
#define SM_A(buf,img)  ((uint32_t)(((buf)*2u + (img)) * A_IMG))          // 0..73728
#define B_IMG   4608u
#define SM_B(buf,img)  ((uint32_t)(73728u + ((buf)*2u + (img)) * B_IMG)) // ..92160
#define SM_IDX  92160u
#define SM_XVo  115200u
#define K1_DYN  138240u

// ---------------------------------------------------------------------------
// prep: l1_w -> bf16 hi/lo 32x64 tile images (row-major, 128B rows).
// tile sid = q*45+f : rows j=0..31, cols k=0..63 -> l1w[j][f*256+q*64+k]
// ---------------------------------------------------------------------------
__global__ __launch_bounds__(128) void prep_kernel(const float* __restrict__ l1w) {
    const int sid = blockIdx.x;          // 0..179
    const int q = sid / 45, f = sid % 45;
    const int t = threadIdx.x;
    if (sid == 0 && t < 128) g_acc[t] = 0.f;
    const int j  = t >> 2;
    const int c0 = (t & 3) * 16;
    const float* src = l1w + (size_t)j * KTOT + f * 256 + q * 64 + c0;
    unsigned char* bh = g_Bh + (size_t)sid * 4096;
    unsigned char* bl = g_Bl + (size_t)sid * 4096;
#pragma unroll
    for (int i = 0; i < 16; i += 2) {
        float a = src[i], b = src[i+1];
        uint32_t h2 = cvt2(b, a);
        float fa = __uint_as_float(h2 << 16);
        float fb = __uint_as_float(h2 & 0xffff0000u);
        uint32_t l2 = cvt2(b - fb, a - fa);
        uint32_t off = (uint32_t)(j * 128 + (c0 + i) * 2);
        *(uint32_t*)(bh + off) = h2;
        *(uint32_t*)(bl + off) = l2;
    }
}

// ---------------------------------------------------------------------------
// k1: 128 blocks (64 sample-tiles x 2 K-splits) x 512 threads (16 warps).
// Per block: x1[128,32] += sum over 90 stages (field f, quarter qg) of
// A(128x64) @ B(32x64)^T, mma.sync bf16 3-term split, software-pipelined:
// LDG(s+1) + cp.async B(s+1) issue before mma(s).
// ---------------------------------------------------------------------------
__global__ void __launch_bounds__(512, 1) k1_kernel(
    const int*   __restrict__ Xi,
    const float* __restrict__ Xv,
    const float* __restrict__ W1,
    const float* __restrict__ W2)
{
    extern __shared__ unsigned char dyn[];
    const uint32_t sbase = smem_u32(dyn);

    const int t    = threadIdx.x;
    const int wid  = t >> 5, lane = t & 31;
    const int tile = blockIdx.x >> 1, ks = blockIdx.x & 1;
    const int n0   = tile * 128;

    int*   sIdx = (int*)(dyn + SM_IDX);
    float* sXv  = (float*)(dyn + SM_XVo);
    for (int i = t; i < 128 * 45; i += 512) {
        const int smp = i / 45, f = i - smp * 45;
        sIdx[i] = Xi[(size_t)(n0 + smp) * 45 + cPERM[f]] + cFOFF[f];
        sXv[i]  = Xv[(size_t)(n0 + smp) * 45 + cPERM[f]];
    }
    __syncthreads();

    // gather role: thread owns sample smp, 16-dim part p of the 64-dim stage
    const int smp = t >> 2, p = t & 3;
    const uint32_t aw = (uint32_t)(smp * 144 + p * 32);

    // mma role: warp = m-stripe (wid&7) x n-half (wid>>3)
    const int wm = wid & 7, nh = wid >> 3;
    const uint32_t a_row = (uint32_t)(wm * 16 + ((lane >> 3) & 1) * 8 + (lane & 7));
    const uint32_t a_col = (uint32_t)((lane >> 4) * 16);
    const uint32_t b_row = (uint32_t)(nh * 16 + (lane & 7) + ((lane >> 4) << 3));
    const uint32_t b_col = (uint32_t)(((lane >> 3) & 1) * 16);

    // B-copy role: thread copies one 16B chunk of one image
    const int cimg = t >> 8;                 // 0=hi, 1=lo
    const int c256 = t & 255;
    const uint32_t bsrc_off = (uint32_t)((c256 >> 3) * 128 + (c256 & 7) * 16);
    const uint32_t bdst_off = (uint32_t)((c256 >> 3) * 144 + (c256 & 7) * 16);
    const unsigned char* gB = cimg ? g_Bl : g_Bh;

    float acc[2][4];
#pragma unroll
    for (int i = 0; i < 2; ++i)
#pragma unroll
        for (int j = 0; j < 4; ++j) acc[i][j] = 0.f;

    float s[16];
#pragma unroll
    for (int i = 0; i < 16; ++i) s[i] = 0.f;
    float sq2 = 0.f, qsum = 0.f, fm1 = 0.f;

    // ---- preloop prefetch: stage 0 ----
    float4 v[4];
    int   idx_cur;
    float xv_cur;
    {
        const int qg0 = ks * 2;
        cpa16(sbase + SM_B(0, cimg) + bdst_off,
              gB + (size_t)(qg0 * 45) * 4096 + bsrc_off);
        cpa_commit();
        idx_cur = sIdx[smp * 45];
        xv_cur  = sXv [smp * 45];
        const float4* src = (const float4*)(W2 + (size_t)idx_cur * 256) + qg0 * 16 + p * 4;
        v[0] = src[0]; v[1] = src[1]; v[2] = src[2]; v[3] = src[3];
    }

    for (int st = 0; st < 90; ++st) {
        const int b = st & 1;
        const int f = (st < 45) ? st : st - 45;

        if (f == 0 && st) {       // quarter boundary: fold FM s-array
            float loc = 0.f;
#pragma unroll
            for (int i = 0; i < 16; ++i) { loc += s[i] * s[i]; s[i] = 0.f; }
            sq2 += loc;
        }
        if (ks == 0 && st < 45 && p == 0) fm1 += W1[idx_cur] * xv_cur;

        // ---- convert prefetched A regs -> smem buf b, accumulate FM ----
        unsigned char* Ah = dyn + SM_A(b, 0);
        unsigned char* Al = dyn + SM_A(b, 1);
#pragma unroll
        for (int i = 0; i < 4; ++i) {
            float4 vv = v[i];
            float e0 = vv.x * xv_cur, e1 = vv.y * xv_cur;
            float e2 = vv.z * xv_cur, e3 = vv.w * xv_cur;
            uint32_t h01 = cvt2(e1, e0), h23 = cvt2(e3, e2);
            float f0 = __uint_as_float(h01 << 16);
            float f1 = __uint_as_float(h01 & 0xffff0000u);
            float f2 = __uint_as_float(h23 << 16);
            float f3 = __uint_as_float(h23 & 0xffff0000u);
            uint32_t l01 = cvt2(e1 - f1, e0 - f0), l23 = cvt2(e3 - f3, e2 - f2);
            *(uint2*)(Ah + aw + i * 8) = make_uint2(h01, h23);
            *(uint2*)(Al + aw + i * 8) = make_uint2(l01, l23);
            const int ii = i * 4;
            s[ii+0] += e0; qsum = fmaf(e0, e0, qsum);
            s[ii+1] += e1; qsum = fmaf(e1, e1, qsum);
            s[ii+2] += e2; qsum = fmaf(e2, e2, qsum);
            s[ii+3] += e3; qsum = fmaf(e3, e3, qsum);
        }

        cpa_wait0();
        __syncthreads();

        // ---- prefetch stage st+1 (LDG + cp.async overlap the mma below) ----
        if (st < 89) {
            const int fn  = (st + 1 < 45) ? st + 1 : st - 44;
            const int qgn = ks * 2 + (st + 1 >= 45);
            cpa16(sbase + SM_B(b ^ 1, cimg) + bdst_off,
                  gB + (size_t)(qgn * 45 + fn) * 4096 + bsrc_off);
            cpa_commit();
            idx_cur = sIdx[smp * 45 + fn];
            xv_cur  = sXv [smp * 45 + fn];
            const float4* src = (const float4*)(W2 + (size_t)idx_cur * 256) + qgn * 16 + p * 4;
            v[0] = src[0]; v[1] = src[1]; v[2] = src[2]; v[3] = src[3];
        }

        // ---- mma phase on buf b ----
        const uint32_t aAh = sbase + SM_A(b, 0) + a_row * 144 + a_col;
        const uint32_t aAl = sbase + SM_A(b, 1) + a_row * 144 + a_col;
        const uint32_t aBh = sbase + SM_B(b, 0) + b_row * 144 + b_col;
        const uint32_t aBl = sbase + SM_B(b, 1) + b_row * 144 + b_col;
#pragma unroll
        for (int k = 0; k < 4; ++k) {
            uint32_t Afh[4], Afl[4], Bh[4], Bl[4];
            ldsm4(Afh, aAh + k * 32);
            ldsm4(Afl, aAl + k * 32);
            ldsm4(Bh,  aBh + k * 32);
            ldsm4(Bl,  aBl + k * 32);
            mma16816(acc[0], Afh, &Bh[0]);
            mma16816(acc[1], Afh, &Bh[2]);
            mma16816(acc[0], Afh, &Bl[0]);
            mma16816(acc[1], Afh, &Bl[2]);
            mma16816(acc[0], Afl, &Bh[0]);
            mma16816(acc[1], Afl, &Bh[2]);
        }
    }

    // fold last quarter
    {
        float loc = 0.f;
#pragma unroll
        for (int i = 0; i < 16; ++i) loc += s[i] * s[i];
        sq2 += loc;
    }

    // FM partial: reduce the 4 part-lanes of each sample
    float val = fm1 + 0.5f * (sq2 - qsum);
    val += __shfl_xor_sync(0xffffffffu, val, 1);
    val += __shfl_xor_sync(0xffffffffu, val, 2);
    if ((t & 3) == 0) g_fmp[ks * NS + n0 + smp] = val;

    // epilogue: write x1 partial from register accumulators
    {
        const int r0 = n0 + wm * 16 + (lane >> 2);
        const int cb = nh * 16 + (lane & 3) * 2;
        float* dst = g_x1p + (size_t)ks * NS * 32;
#pragma unroll
        for (int nt = 0; nt < 2; ++nt) {
            const int c = cb + nt * 8;
            *(float2*)(dst + (size_t)r0       * 32 + c) = make_float2(acc[nt][0], acc[nt][1]);
            *(float2*)(dst + (size_t)(r0 + 8) * 32 + c) = make_float2(acc[nt][2], acc[nt][3]);
        }
    }
}

// ---------------------------------------------------------------------------
// stats: column sum / sumsq of (a [+ b]) accumulated via atomics into g_acc.
// 256 blocks x 256 threads, 32 rows per block.
// ---------------------------------------------------------------------------
__global__ __launch_bounds__(256) void stats_kernel(const float* __restrict__ a,
                                                    const float* __restrict__ b,
                                                    float* __restrict__ sum,
                                                    float* __restrict__ ss)
{
    const int t = threadIdx.x, col = t & 31, w = t >> 5;
    const int rbase = blockIdx.x * 32;
    float s = 0.f, sq = 0.f;
#pragma unroll
    for (int i = 0; i < 4; ++i) {
        const size_t r = rbase + w + i * 8;
        float v = a[r * 32 + col];
        if (b) v += b[r * 32 + col];
        s += v; sq += v * v;
    }
    __shared__ float sS[32], sQ[32];
    if (t < 32) { sS[t] = 0.f; sQ[t] = 0.f; }
    __syncthreads();
    atomicAdd(&sS[col], s); atomicAdd(&sQ[col], sq);
    __syncthreads();
    if (t < 32) { atomicAdd(&sum[t], sS[t]); atomicAdd(&ss[t], sQ[t]); }
}

// ---------------------------------------------------------------------------
// layer2: h = BN1(x1a+x1b); x2 = h @ l2_w^T + l2_b.
// 1024 blocks x 256 threads; thread = (sample, output j).
// ---------------------------------------------------------------------------
__global__ __launch_bounds__(256) void layer2_kernel(const float* __restrict__ l2w,
                                                     const float* __restrict__ l2b,
                                                     const float* __restrict__ bn1g,
                                                     const float* __restrict__ bn1b)
{
    __shared__ float swT[1024], hbuf[256], sm[32], ssc[32], sbb[32], sb[32];
    const int t = threadIdx.x;
#pragma unroll
    for (int i = t; i < 1024; i += 256)
        swT[(i & 31) * 32 + (i >> 5)] = l2w[i];      // transposed: swT[i][j]
    if (t < 32) {
        float m   = g_acc[t] * (1.f / NS);
        float var = g_acc[32 + t] * (1.f / NS) - m * m;
        sm[t] = m; ssc[t] = bn1g[t] * rsqrtf(var + 1e-5f);
        sbb[t] = bn1b[t]; sb[t] = l2b[t];
    }
    __syncthreads();

    const int n0 = blockIdx.x * 8;
    const int sl = t >> 5, col = t & 31;
    {
        const size_t r = n0 + sl;
        float x = g_x1p[r * 32 + col] + g_x1p[(NS + r) * 32 + col];
        hbuf[sl * 32 + col] = (x - sm[col]) * ssc[col] + sbb[col];
    }
    __syncthreads();

    float a = sb[col];
    const float* hrow = &hbuf[sl * 32];
#pragma unroll
    for (int i = 0; i < 32; ++i) a = fmaf(hrow[i], swT[i * 32 + col], a);
    g_x2[(size_t)(n0 + sl) * 32 + col] = a;
}

// ---------------------------------------------------------------------------
// final: out = fm partials + sum_j BN2(x2) + bias
// ---------------------------------------------------------------------------
__global__ __launch_bounds__(256) void final_kernel(const float* __restrict__ bias,
                                                    const float* __restrict__ bn2g,
                                                    const float* __restrict__ bn2b,
                                                    float* __restrict__ out)
{
    __shared__ float sm[32], ssc[32], sbb[32];
    const int t = threadIdx.x;
    if (t < 32) {
        float m   = g_acc[64 + t] * (1.f / NS);
        float var = g_acc[96 + t] * (1.f / NS) - m * m;
        sm[t] = m; ssc[t] = bn2g[t] * rsqrtf(var + 1e-5f); sbb[t] = bn2b[t];
    }
    __syncthreads();
    const int n = blockIdx.x * 256 + t;
    float a = g_fmp[n] + g_fmp[NS + n] + bias[0];
    const float* x = g_x2 + (size_t)n * 32;
#pragma unroll
    for (int j = 0; j < 32; ++j) a += (x[j] - sm[j]) * ssc[j] + sbb[j];
    out[n] = a;
}

// ---------------------------------------------------------------------------
extern "C" void kernel_launch(void* const* d_in, const int* in_sizes, int n_in,
                              void* d_out, int out_size)
{
    const int*   Xi    = (const int*)  d_in[0];
    const float* Xv    = (const float*)d_in[1];
    const float* W1    = (const float*)d_in[2];
    const float* W2    = (const float*)d_in[3];
    const float* bias  = (const float*)d_in[4];
    const float* l1_w  = (const float*)d_in[5];
    // d_in[6] = l1_b: cancels exactly inside BN1
    const float* bn1_g = (const float*)d_in[7];
    const float* bn1_b = (const float*)d_in[8];
    const float* l2_w  = (const float*)d_in[9];
    const float* l2_b  = (const float*)d_in[10];
    const float* bn2_g = (const float*)d_in[11];
    const float* bn2_b = (const float*)d_in[12];
    float* out = (float*)d_out;

    cudaFuncSetAttribute(k1_kernel, cudaFuncAttributeMaxDynamicSharedMemorySize, K1_DYN);

    float *x1p, *x2p, *accp;
    cudaGetSymbolAddress((void**)&x1p,  g_x1p);
    cudaGetSymbolAddress((void**)&x2p,  g_x2);
    cudaGetSymbolAddress((void**)&accp, g_acc);

    prep_kernel<<<180, 128>>>(l1_w);
    k1_kernel<<<128, 512, K1_DYN>>>(Xi, Xv, W1, W2);
    stats_kernel<<<256, 256>>>(x1p, x1p + (size_t)NS * 32, accp, accp + 32);
    layer2_kernel<<<1024, 256>>>(l2_w, l2_b, bn1_g, bn1_b);
    stats_kernel<<<256, 256>>>(x2p, (const float*)nullptr, accp + 64, accp + 96);
    final_kernel<<<32, 256>>>(bias, bn2_g, bn2_b, out);
}

// round 6
// speedup vs baseline: 4.7709x; 1.0288x over previous
#include <cuda_runtime.h>
#include <cuda_bf16.h>
#include <cstdint>
#include <cstddef>

#define NS   8192
#define KTOT 11520

__constant__ int cPERM[45] = {
    0,1,2,3,4,5,6, 7,8,9,
    10,11,12,13,14,15,16,17,18,19,20,21,22,23,
    26,27, 28,29, 24,25,
    30,31,32,33,34,35,36,37,38,39,40,41,42,43,44
};
__constant__ int cFOFF[45] = {
    0,300,1300,2300,2800,2950,2962,
    2993,2993,2993,
    3023,3023,3023,3023,3023,3023,3023,3023,3023,3023,3023,3023,3023,3023,
    3223,3223, 53223,53223, 103223,103223,
    123223,123223,123223,123223,123223,123223,123223,123223,
    123223,123223,123223,123223,123223,123223,123223
};

// device-global scratch (no cudaMalloc allowed)
__device__ float g_x1p[2*NS*32];
__device__ float g_x2[NS*32];
__device__ float g_fmp[2*NS];
__device__ float g_acc[128];                 // [sum1|ss1|sum2|ss2] x32
__device__ __align__(16) unsigned char g_Bh[180*4096];   // l1_w hi tiles 32x64 bf16
__device__ __align__(16) unsigned char g_Bl[180*4096];   // l1_w lo tiles

// ---------------- helpers ----------------
__device__ __forceinline__ uint32_t smem_u32(const void* p) {
    uint32_t r;
    asm("{ .reg .u64 t; cvta.to.shared.u64 t, %1; cvt.u32.u64 %0, t; }"
        : "=r"(r) : "l"(p));
    return r;
}
// pack two f32 -> bf16x2 (second arg -> low half)
__device__ __forceinline__ uint32_t cvt2(float hi, float lo) {
    uint32_t r;
    asm("cvt.rn.bf16x2.f32 %0, %1, %2;" : "=r"(r) : "f"(hi), "f"(lo));
    return r;
}
__device__ __forceinline__ void ldsm4(uint32_t* r, uint32_t addr) {
    asm volatile("ldmatrix.sync.aligned.m8n8.x4.shared.b16 {%0,%1,%2,%3}, [%4];"
        : "=r"(r[0]), "=r"(r[1]), "=r"(r[2]), "=r"(r[3]) : "r"(addr));
}
__device__ __forceinline__ void mma16816(float* d, const uint32_t* a, const uint32_t* b) {
    asm volatile(
        "mma.sync.aligned.m16n8k16.row.col.f32.bf16.bf16.f32 "
        "{%0,%1,%2,%3}, {%4,%5,%6,%7}, {%8,%9}, {%0,%1,%2,%3};"
        : "+f"(d[0]), "+f"(d[1]), "+f"(d[2]), "+f"(d[3])
        : "r"(a[0]), "r"(a[1]), "r"(a[2]), "r"(a[3]), "r"(b[0]), "r"(b[1]));
}
__device__ __forceinline__ void cpa16(uint32_t dst, const void* src) {
    asm volatile("cp.async.cg.shared.global [%0], [%1], 16;" :: "r"(dst), "l"(src));
}
__device__ __forceinline__ void cpa_commit() {
    asm volatile("cp.async.commit_group;" ::: "memory");
}
__device__ __forceinline__ void cpa_wait0() {
    asm volatile("cp.async.wait_group 0;" ::: "memory");
}

// ---------------- smem layout (byte offsets into dynamic smem) ----------------
// A tiles: 64 rows x 144B (64 bf16 + pad), hi/lo, double buffered
#define A_IMG   9216u
#define SM_A(buf,img)  ((uint32_t)(((buf)*2u + (img)) * A_IMG))          // 0..36864
#define B_IMG   4608u
#define SM_B(buf,img)  ((uint32_t)(36864u + ((buf)*2u + (img)) * B_IMG)) // ..55296
#define SM_IDX  55296u
#define SM_XVo  66816u
#define K1_DYN  78336u

// ---------------------------------------------------------------------------
// prep: l1_w -> bf16 hi/lo 32x64 tile images (row-major, 128B rows).
// tile sid = q*45+f : rows j=0..31, cols k=0..63 -> l1w[j][f*256+q*64+k]
// ---------------------------------------------------------------------------
__global__ __launch_bounds__(128) void prep_kernel(const float* __restrict__ l1w) {
    const int sid = blockIdx.x;          // 0..179
    const int q = sid / 45, f = sid % 45;
    const int t = threadIdx.x;
    if (sid == 0 && t < 128) g_acc[t] = 0.f;
    const int j  = t >> 2;
    const int c0 = (t & 3) * 16;
    const float* src = l1w + (size_t)j * KTOT + f * 256 + q * 64 + c0;
    unsigned char* bh = g_Bh + (size_t)sid * 4096;
    unsigned char* bl = g_Bl + (size_t)sid * 4096;
#pragma unroll
    for (int i = 0; i < 16; i += 2) {
        float a = src[i], b = src[i+1];
        uint32_t h2 = cvt2(b, a);
        float fa = __uint_as_float(h2 << 16);
        float fb = __uint_as_float(h2 & 0xffff0000u);
        uint32_t l2 = cvt2(b - fb, a - fa);
        uint32_t off = (uint32_t)(j * 128 + (c0 + i) * 2);
        *(uint32_t*)(bh + off) = h2;
        *(uint32_t*)(bl + off) = l2;
    }
}

// ---------------------------------------------------------------------------
// k1: 256 blocks (128 sample-tiles x 2 K-splits) x 256 threads (8 warps),
// 2 CTAs/SM. Per block: x1[64,32] += sum over 90 stages (field f, quarter qg)
// of A(64x64) @ B(32x64)^T, mma.sync bf16 3-term split, software-pipelined.
// ---------------------------------------------------------------------------
__global__ void __launch_bounds__(256, 2) k1_kernel(
    const int*   __restrict__ Xi,
    const float* __restrict__ Xv,
    const float* __restrict__ W1,
    const float* __restrict__ W2)
{
    extern __shared__ unsigned char dyn[];
    const uint32_t sbase = smem_u32(dyn);

    const int t    = threadIdx.x;
    const int wid  = t >> 5, lane = t & 31;
    const int tile = blockIdx.x >> 1, ks = blockIdx.x & 1;
    const int n0   = tile * 64;

    int*   sIdx = (int*)(dyn + SM_IDX);
    float* sXv  = (float*)(dyn + SM_XVo);
    for (int i = t; i < 64 * 45; i += 256) {
        const int smp = i / 45, f = i - smp * 45;
        sIdx[i] = Xi[(size_t)(n0 + smp) * 45 + cPERM[f]] + cFOFF[f];
        sXv[i]  = Xv[(size_t)(n0 + smp) * 45 + cPERM[f]];
    }
    __syncthreads();

    // gather role: thread owns sample smp, 16-dim part p of the 64-dim stage
    const int smp = t >> 2, p = t & 3;
    const uint32_t aw = (uint32_t)(smp * 144 + p * 32);

    // mma role: warp = m-stripe (wid&3) x n-half (wid>>2)
    const int wm = wid & 3, nh = wid >> 2;
    const uint32_t a_row = (uint32_t)(wm * 16 + ((lane >> 3) & 1) * 8 + (lane & 7));
    const uint32_t a_col = (uint32_t)((lane >> 4) * 16);
    const uint32_t b_row = (uint32_t)(nh * 16 + (lane & 7) + ((lane >> 4) << 3));
    const uint32_t b_col = (uint32_t)(((lane >> 3) & 1) * 16);

    float acc[2][4];
#pragma unroll
    for (int i = 0; i < 2; ++i)
#pragma unroll
        for (int j = 0; j < 4; ++j) acc[i][j] = 0.f;

    float s[16];
#pragma unroll
    for (int i = 0; i < 16; ++i) s[i] = 0.f;
    float sq2 = 0.f, qsum = 0.f, fm1 = 0.f;

    // ---- preloop prefetch: stage 0 ----
    float4 v[4];
    int   idx_cur;
    float xv_cur;
    {
        const int qg0 = ks * 2;
        const unsigned char* srcB = g_Bh + (size_t)(qg0 * 45) * 4096;
        const unsigned char* srcBl = g_Bl + (size_t)(qg0 * 45) * 4096;
#pragma unroll
        for (int i = 0; i < 2; ++i) {
            const int id = t + i * 256;
            const int img = id >> 8, c = id & 255;
            const uint32_t so = (uint32_t)((c >> 3) * 128 + (c & 7) * 16);
            const uint32_t dc = (uint32_t)((c >> 3) * 144 + (c & 7) * 16);
            cpa16(sbase + SM_B(0, img) + dc, (img ? srcBl : srcB) + so);
        }
        cpa_commit();
        idx_cur = sIdx[smp * 45];
        xv_cur  = sXv [smp * 45];
        const float4* src = (const float4*)(W2 + (size_t)idx_cur * 256) + qg0 * 16 + p * 4;
        v[0] = src[0]; v[1] = src[1]; v[2] = src[2]; v[3] = src[3];
    }

    for (int st = 0; st < 90; ++st) {
        const int b = st & 1;
        const int f = (st < 45) ? st : st - 45;

        if (f == 0 && st) {       // quarter boundary: fold FM s-array
            float loc = 0.f;
#pragma unroll
            for (int i = 0; i < 16; ++i) { loc += s[i] * s[i]; s[i] = 0.f; }
            sq2 += loc;
        }
        if (ks == 0 && st < 45 && p == 0) fm1 += W1[idx_cur] * xv_cur;

        // ---- convert prefetched A regs -> smem buf b, accumulate FM ----
        unsigned char* Ah = dyn + SM_A(b, 0);
        unsigned char* Al = dyn + SM_A(b, 1);
#pragma unroll
        for (int i = 0; i < 4; ++i) {
            float4 vv = v[i];
            float e0 = vv.x * xv_cur, e1 = vv.y * xv_cur;
            float e2 = vv.z * xv_cur, e3 = vv.w * xv_cur;
            uint32_t h01 = cvt2(e1, e0), h23 = cvt2(e3, e2);
            float f0 = __uint_as_float(h01 << 16);
            float f1 = __uint_as_float(h01 & 0xffff0000u);
            float f2 = __uint_as_float(h23 << 16);
            float f3 = __uint_as_float(h23 & 0xffff0000u);
            uint32_t l01 = cvt2(e1 - f1, e0 - f0), l23 = cvt2(e3 - f3, e2 - f2);
            *(uint2*)(Ah + aw + i * 8) = make_uint2(h01, h23);
            *(uint2*)(Al + aw + i * 8) = make_uint2(l01, l23);
            const int ii = i * 4;
            s[ii+0] += e0; qsum = fmaf(e0, e0, qsum);
            s[ii+1] += e1; qsum = fmaf(e1, e1, qsum);
            s[ii+2] += e2; qsum = fmaf(e2, e2, qsum);
            s[ii+3] += e3; qsum = fmaf(e3, e3, qsum);
        }

        cpa_wait0();
        __syncthreads();

        // ---- prefetch stage st+1 (LDG + cp.async overlap the mma below) ----
        if (st < 89) {
            const int fn  = (st + 1 < 45) ? st + 1 : st - 44;
            const int qgn = ks * 2 + (st + 1 >= 45);
            const unsigned char* srcB  = g_Bh + (size_t)(qgn * 45 + fn) * 4096;
            const unsigned char* srcBl = g_Bl + (size_t)(qgn * 45 + fn) * 4096;
#pragma unroll
            for (int i = 0; i < 2; ++i) {
                const int id = t + i * 256;
                const int img = id >> 8, c = id & 255;
                const uint32_t so = (uint32_t)((c >> 3) * 128 + (c & 7) * 16);
                const uint32_t dc = (uint32_t)((c >> 3) * 144 + (c & 7) * 16);
                cpa16(sbase + SM_B(b ^ 1, img) + dc, (img ? srcBl : srcB) + so);
            }
            cpa_commit();
            idx_cur = sIdx[smp * 45 + fn];
            xv_cur  = sXv [smp * 45 + fn];
            const float4* src = (const float4*)(W2 + (size_t)idx_cur * 256) + qgn * 16 + p * 4;
            v[0] = src[0]; v[1] = src[1]; v[2] = src[2]; v[3] = src[3];
        }

        // ---- mma phase on buf b ----
        const uint32_t aAh = sbase + SM_A(b, 0) + a_row * 144 + a_col;
        const uint32_t aAl = sbase + SM_A(b, 1) + a_row * 144 + a_col;
        const uint32_t aBh = sbase + SM_B(b, 0) + b_row * 144 + b_col;
        const uint32_t aBl = sbase + SM_B(b, 1) + b_row * 144 + b_col;
#pragma unroll
        for (int k = 0; k < 4; ++k) {
            uint32_t Afh[4], Afl[4], Bh[4], Bl[4];
            ldsm4(Afh, aAh + k * 32);
            ldsm4(Afl, aAl + k * 32);
            ldsm4(Bh,  aBh + k * 32);
            ldsm4(Bl,  aBl + k * 32);
            mma16816(acc[0], Afh, &Bh[0]);
            mma16816(acc[1], Afh, &Bh[2]);
            mma16816(acc[0], Afh, &Bl[0]);
            mma16816(acc[1], Afh, &Bl[2]);
            mma16816(acc[0], Afl, &Bh[0]);
            mma16816(acc[1], Afl, &Bh[2]);
        }
    }

    // fold last quarter
    {
        float loc = 0.f;
#pragma unroll
        for (int i = 0; i < 16; ++i) loc += s[i] * s[i];
        sq2 += loc;
    }

    // FM partial: reduce the 4 part-lanes of each sample
    float val = fm1 + 0.5f * (sq2 - qsum);
    val += __shfl_xor_sync(0xffffffffu, val, 1);
    val += __shfl_xor_sync(0xffffffffu, val, 2);
    if ((t & 3) == 0) g_fmp[ks * NS + n0 + smp] = val;

    // epilogue: write x1 partial from register accumulators
    {
        const int r0 = n0 + wm * 16 + (lane >> 2);
        const int cb = nh * 16 + (lane & 3) * 2;
        float* dst = g_x1p + (size_t)ks * NS * 32;
#pragma unroll
        for (int nt = 0; nt < 2; ++nt) {
            const int c = cb + nt * 8;
            *(float2*)(dst + (size_t)r0       * 32 + c) = make_float2(acc[nt][0], acc[nt][1]);
            *(float2*)(dst + (size_t)(r0 + 8) * 32 + c) = make_float2(acc[nt][2], acc[nt][3]);
        }
    }
}

// ---------------------------------------------------------------------------
// stats: column sum / sumsq of (a + b) accumulated via atomics into g_acc.
// 256 blocks x 256 threads, 32 rows per block.
// ---------------------------------------------------------------------------
__global__ __launch_bounds__(256) void stats_kernel(const float* __restrict__ a,
                                                    const float* __restrict__ b,
                                                    float* __restrict__ sum,
                                                    float* __restrict__ ss)
{
    const int t = threadIdx.x, col = t & 31, w = t >> 5;
    const int rbase = blockIdx.x * 32;
    float s = 0.f, sq = 0.f;
#pragma unroll
    for (int i = 0; i < 4; ++i) {
        const size_t r = rbase + w + i * 8;
        float v = a[r * 32 + col] + b[r * 32 + col];
        s += v; sq += v * v;
    }
    __shared__ float sS[32], sQ[32];
    if (t < 32) { sS[t] = 0.f; sQ[t] = 0.f; }
    __syncthreads();
    atomicAdd(&sS[col], s); atomicAdd(&sQ[col], sq);
    __syncthreads();
    if (t < 32) { atomicAdd(&sum[t], sS[t]); atomicAdd(&ss[t], sQ[t]); }
}

// ---------------------------------------------------------------------------
// layer2: h = BN1(x1a+x1b); x2 = h @ l2_w^T + l2_b, with fused BN2 stats.
// 1024 blocks x 256 threads; thread = (sample, output j).
// ---------------------------------------------------------------------------
__global__ __launch_bounds__(256) void layer2_kernel(const float* __restrict__ l2w,
                                                     const float* __restrict__ l2b,
                                                     const float* __restrict__ bn1g,
                                                     const float* __restrict__ bn1b)
{
    __shared__ float swT[1024], hbuf[256], sm[32], ssc[32], sbb[32], sb[32];
    __shared__ float sS[32], sQ[32];
    const int t = threadIdx.x;
#pragma unroll
    for (int i = t; i < 1024; i += 256)
        swT[(i & 31) * 32 + (i >> 5)] = l2w[i];      // transposed: swT[i][j]
    if (t < 32) {
        float m   = g_acc[t] * (1.f / NS);
        float var = g_acc[32 + t] * (1.f / NS) - m * m;
        sm[t] = m; ssc[t] = bn1g[t] * rsqrtf(var + 1e-5f);
        sbb[t] = bn1b[t]; sb[t] = l2b[t];
        sS[t] = 0.f; sQ[t] = 0.f;
    }
    __syncthreads();

    const int n0 = blockIdx.x * 8;
    const int sl = t >> 5, col = t & 31;
    {
        const size_t r = n0 + sl;
        float x = g_x1p[r * 32 + col] + g_x1p[(NS + r) * 32 + col];
        hbuf[sl * 32 + col] = (x - sm[col]) * ssc[col] + sbb[col];
    }
    __syncthreads();

    float a = sb[col];
    const float* hrow = &hbuf[sl * 32];
#pragma unroll
    for (int i = 0; i < 32; ++i) a = fmaf(hrow[i], swT[i * 32 + col], a);
    g_x2[(size_t)(n0 + sl) * 32 + col] = a;

    // fused BN2 stats
    atomicAdd(&sS[col], a);
    atomicAdd(&sQ[col], a * a);
    __syncthreads();
    if (t < 32) {
        atomicAdd(&g_acc[64 + t], sS[t]);
        atomicAdd(&g_acc[96 + t], sQ[t]);
    }
}

// ---------------------------------------------------------------------------
// final: out = fm partials + sum_j BN2(x2) + bias
// ---------------------------------------------------------------------------
__global__ __launch_bounds__(256) void final_kernel(const float* __restrict__ bias,
                                                    const float* __restrict__ bn2g,
                                                    const float* __restrict__ bn2b,
                                                    float* __restrict__ out)
{
    __shared__ float sm[32], ssc[32], sbb[32];
    const int t = threadIdx.x;
    if (t < 32) {
        float m   = g_acc[64 + t] * (1.f / NS);
        float var = g_acc[96 + t] * (1.f / NS) - m * m;
        sm[t] = m; ssc[t] = bn2g[t] * rsqrtf(var + 1e-5f); sbb[t] = bn2b[t];
    }
    __syncthreads();
    const int n = blockIdx.x * 256 + t;
    float a = g_fmp[n] + g_fmp[NS + n] + bias[0];
    const float* x = g_x2 + (size_t)n * 32;
#pragma unroll
    for (int j = 0; j < 32; ++j) a += (x[j] - sm[j]) * ssc[j] + sbb[j];
    out[n] = a;
}

// ---------------------------------------------------------------------------
extern "C" void kernel_launch(void* const* d_in, const int* in_sizes, int n_in,
                              void* d_out, int out_size)
{
    const int*   Xi    = (const int*)  d_in[0];
    const float* Xv    = (const float*)d_in[1];
    const float* W1    = (const float*)d_in[2];
    const float* W2    = (const float*)d_in[3];
    const float* bias  = (const float*)d_in[4];
    const float* l1_w  = (const float*)d_in[5];
    // d_in[6] = l1_b: cancels exactly inside BN1
    const float* bn1_g = (const float*)d_in[7];
    const float* bn1_b = (const float*)d_in[8];
    const float* l2_w  = (const float*)d_in[9];
    const float* l2_b  = (const float*)d_in[10];
    const float* bn2_g = (const float*)d_in[11];
    const float* bn2_b = (const float*)d_in[12];
    float* out = (float*)d_out;

    cudaFuncSetAttribute(k1_kernel, cudaFuncAttributeMaxDynamicSharedMemorySize, K1_DYN);

    float *x1p, *accp;
    cudaGetSymbolAddress((void**)&x1p,  g_x1p);
    cudaGetSymbolAddress((void**)&accp, g_acc);

    prep_kernel<<<180, 128>>>(l1_w);
    k1_kernel<<<256, 256, K1_DYN>>>(Xi, Xv, W1, W2);
    stats_kernel<<<256, 256>>>(x1p, x1p + (size_t)NS * 32, accp, accp + 32);
    layer2_kernel<<<1024, 256>>>(l2_w, l2_b, bn1_g, bn1_b);
    final_kernel<<<32, 256>>>(bias, bn2_g, bn2_b, out);
}